// round 16
// baseline (speedup 1.0000x reference)
#include <cuda_runtime.h>
#include <cuda_bf16.h>
#include <math.h>
#include <stddef.h>

#define BATCH  64
#define NTOK   4096
#define DIM    256
#define SDIM   256
#define KSLOT  8
#define EPSA   1e-8f
#define LNEPS  1e-5f
#define NROWS  (BATCH*NTOK)       /* 262144 */
#define NCHUNK 8                  /* 512 tokens per chunk */

/* ------------- scratch (device globals; no allocation allowed) ---------- */
__device__ __align__(16) __nv_bfloat16 g_Ah[(size_t)NROWS*DIM];    /* 128 MB */
__device__ __align__(16) __nv_bfloat16 g_Wvf[256*256];
__device__ __align__(16) float g_cbk[256];
__device__ __align__(16) float g_cbv[256];
__device__ __align__(16) __nv_bfloat16 g_MbT[256*256];
__device__ __align__(16) float g_m0[256];
__device__ __align__(16) float g_slots[BATCH*KSLOT*SDIM];
__device__ __align__(16) __nv_bfloat16 g_Xb[512*256];
__device__ __align__(16) __nv_bfloat16 g_qkb[BATCH*KSLOT*DIM];
__device__ __align__(16) float g_qk0[BATCH*KSLOT];
__device__ __align__(16) float g_updpart[NCHUNK*BATCH*KSLOT*DIM];  /* 4 MB */
__device__ __align__(16) float g_cspart[BATCH*NCHUNK*KSLOT];

__device__ __forceinline__ float sigmoidf_(float x){ return 1.0f/(1.0f + expf(-x)); }
__device__ __forceinline__ float dot4_(float4 a, float4 b){
    return a.x*b.x + a.y*b.y + a.z*b.z + a.w*b.w;
}

/* ----------------------- PTX helpers ----------------------------------- */
__device__ __forceinline__ unsigned smem_u32(const void* p){
    return (unsigned)__cvta_generic_to_shared(p);
}
__device__ __forceinline__ void cp16(unsigned dst, const void* src){
    asm volatile("cp.async.cg.shared.global [%0],[%1],16;\n"::"r"(dst),"l"(src));
}
__device__ __forceinline__ void cp_commit(){ asm volatile("cp.async.commit_group;\n"::); }
__device__ __forceinline__ void cp_wait2(){ asm volatile("cp.async.wait_group 2;\n"::); }
__device__ __forceinline__ void cp_wait1(){ asm volatile("cp.async.wait_group 1;\n"::); }
__device__ __forceinline__ void cp_wait0(){ asm volatile("cp.async.wait_group 0;\n"::); }
__device__ __forceinline__ void ldm4(unsigned&r0,unsigned&r1,unsigned&r2,unsigned&r3,unsigned a){
    asm volatile("ldmatrix.sync.aligned.m8n8.x4.shared.b16 {%0,%1,%2,%3},[%4];\n"
        :"=r"(r0),"=r"(r1),"=r"(r2),"=r"(r3):"r"(a));
}
__device__ __forceinline__ void ldm4t(unsigned&r0,unsigned&r1,unsigned&r2,unsigned&r3,unsigned a){
    asm volatile("ldmatrix.sync.aligned.m8n8.x4.trans.shared.b16 {%0,%1,%2,%3},[%4];\n"
        :"=r"(r0),"=r"(r1),"=r"(r2),"=r"(r3):"r"(a));
}
__device__ __forceinline__ void mma16816(float* c, const unsigned* a, unsigned b0, unsigned b1){
    asm volatile("mma.sync.aligned.m16n8k16.row.col.f32.bf16.bf16.f32 "
        "{%0,%1,%2,%3},{%4,%5,%6,%7},{%8,%9},{%0,%1,%2,%3};\n"
        :"+f"(c[0]),"+f"(c[1]),"+f"(c[2]),"+f"(c[3])
        :"r"(a[0]),"r"(a[1]),"r"(a[2]),"r"(a[3]),"r"(b0),"r"(b1));
}

/* ---------------------- 1. slots = mu + exp(ls)*noise ------------------- */
__global__ void k_init_slots(const float* __restrict__ noise,
                             const float* __restrict__ mu,
                             const float* __restrict__ lsig){
    int i = blockIdx.x*256 + threadIdx.x;
    int s = i & (SDIM-1);
    g_slots[i] = mu[s] + expf(lsig[s]) * noise[i];
}

/* ------------- 2. LN(inputs, no affine) -> bf16 ------------------------ */
__global__ __launch_bounds__(256) void k_prep_a(const float* __restrict__ inp){
    int row  = blockIdx.x*8 + (threadIdx.x >> 5);
    int lane = threadIdx.x & 31;
    const float4* p = (const float4*)(inp + (size_t)row*DIM);
    float4 a = p[lane*2], b = p[lane*2+1];
    float x[8] = {a.x,a.y,a.z,a.w,b.x,b.y,b.z,b.w};
    float s = 0.f, q = 0.f;
#pragma unroll
    for (int i=0;i<8;i++){ s += x[i]; q += x[i]*x[i]; }
#pragma unroll
    for (int o=16;o;o>>=1){
        s += __shfl_xor_sync(0xffffffffu, s, o);
        q += __shfl_xor_sync(0xffffffffu, q, o);
    }
    float m = s*(1.0f/DIM);
    float rstd = rsqrtf(q*(1.0f/DIM) - m*m + LNEPS);
    __nv_bfloat162 h2[4];
#pragma unroll
    for (int i=0;i<4;i++){
        h2[i] = __halves2bfloat162(__float2bfloat16((x[2*i]-m)*rstd),
                                   __float2bfloat16((x[2*i+1]-m)*rstd));
    }
    size_t off = (size_t)row*DIM + lane*8;
    *(uint4*)(g_Ah + off) = *(uint4*)h2;
}

/* ------------- 3. weight prep: fold gamma/beta/scale -------------------- */
__global__ __launch_bounds__(256) void k_prep_w(const float* __restrict__ Wk,
        const float* __restrict__ Wv, const float* __restrict__ gin,
        const float* __restrict__ bin){
    __shared__ float rk[8], rv[8];
    int s = blockIdx.x, d = threadIdx.x;
    int w = d>>5, l = d&31;
    float gk = gin[d], bt = bin[d];
    float wk = Wk[s*256+d], wv = Wv[s*256+d];
    g_Wvf[s*256+d] = __float2bfloat16(wv*gk);
    float pk = wk*bt, pv = wv*bt;
#pragma unroll
    for (int o=16;o;o>>=1){
        pk += __shfl_xor_sync(0xffffffffu, pk, o);
        pv += __shfl_xor_sync(0xffffffffu, pv, o);
    }
    if (l==0){ rk[w]=pk; rv[w]=pv; }
    __syncthreads();
    if (d==0){
        float sk=0.f, sv=0.f;
#pragma unroll
        for (int i=0;i<8;i++){ sk+=rk[i]; sv+=rv[i]; }
        g_cbk[s] = sk*0.0625f;
        g_cbv[s] = sv;
    }
}

/* ------------- 3b. tiled GEMM: MbT[d][e] = Sum_s Wq[s,e]Wk[s,d]g[d]/16 -- */
__global__ __launch_bounds__(256) void k_prep_m(const float* __restrict__ Wq,
        const float* __restrict__ Wk, const float* __restrict__ gin){
    __shared__ float As[32][64];
    __shared__ float Bs[32][64];
    int e0 = blockIdx.x*64, d0 = blockIdx.y*64;
    int tid = threadIdx.x;
    int tx = tid&15, ty = tid>>4;
    int lr = tid>>3, lc = (tid&7)*8;
    float acc[4][4];
#pragma unroll
    for (int i=0;i<4;i++)
#pragma unroll
        for (int j=0;j<4;j++) acc[i][j]=0.f;
    for (int s0=0;s0<256;s0+=32){
        *(float4*)&As[lr][lc]   = *(const float4*)(Wq + (size_t)(s0+lr)*256 + e0 + lc);
        *(float4*)&As[lr][lc+4] = *(const float4*)(Wq + (size_t)(s0+lr)*256 + e0 + lc + 4);
        *(float4*)&Bs[lr][lc]   = *(const float4*)(Wk + (size_t)(s0+lr)*256 + d0 + lc);
        *(float4*)&Bs[lr][lc+4] = *(const float4*)(Wk + (size_t)(s0+lr)*256 + d0 + lc + 4);
        __syncthreads();
#pragma unroll
        for (int s=0;s<32;s++){
            float4 av = *(const float4*)&As[s][ty*4];
            float4 bv = *(const float4*)&Bs[s][tx*4];
            float a[4] = {av.x,av.y,av.z,av.w};
            float b[4] = {bv.x,bv.y,bv.z,bv.w};
#pragma unroll
            for (int i=0;i<4;i++)
#pragma unroll
                for (int j=0;j<4;j++) acc[i][j] += a[i]*b[j];
        }
        __syncthreads();
    }
#pragma unroll
    for (int j=0;j<4;j++){
        int d = d0 + tx*4 + j;
        float gd = gin[d]*0.0625f;
        __nv_bfloat162 p0 = __halves2bfloat162(
            __float2bfloat16(acc[0][j]*gd), __float2bfloat16(acc[1][j]*gd));
        __nv_bfloat162 p1 = __halves2bfloat162(
            __float2bfloat16(acc[2][j]*gd), __float2bfloat16(acc[3][j]*gd));
        *(__nv_bfloat162*)(g_MbT + (size_t)d*256 + e0 + ty*4)     = p0;
        *(__nv_bfloat162*)(g_MbT + (size_t)d*256 + e0 + ty*4 + 2) = p1;
    }
}

/* ------------- 3c. m0[e] = Sum_s Wq[s,e]*cbk[s]  (1 block) -------------- */
__global__ __launch_bounds__(256) void k_prep_m0(const float* __restrict__ Wq){
    __shared__ float cb[256];
    int e = threadIdx.x;
    cb[e] = g_cbk[e];
    __syncthreads();
    float p=0.f;
#pragma unroll 4
    for (int s=0;s<256;s++) p += Wq[(size_t)s*256+e]*cb[s];
    g_m0[e] = p;
}

/* ------------- 4a. X = LN(slots)*gsl+bsl -> bf16 ; qk0 = X·m0 ----------- */
__global__ __launch_bounds__(256) void k_ln_slots(const float* __restrict__ gsl,
                                                  const float* __restrict__ bsl){
    int b = blockIdx.x, t = threadIdx.x, w = t>>5, l = t&31;
    const float4* sr = (const float4*)(g_slots + (b*8+w)*256);
    float4 a = sr[l*2], c = sr[l*2+1];
    float v[8] = {a.x,a.y,a.z,a.w,c.x,c.y,c.z,c.w};
    float s=0.f, q=0.f;
#pragma unroll
    for (int i=0;i<8;i++){ s+=v[i]; q+=v[i]*v[i]; }
#pragma unroll
    for (int o=16;o;o>>=1){
        s += __shfl_xor_sync(0xffffffffu, s, o);
        q += __shfl_xor_sync(0xffffffffu, q, o);
    }
    float m = s*(1.0f/256.f);
    float rstd = rsqrtf(q*(1.0f/256.f)-m*m+LNEPS);
    float4 g0 = ((const float4*)gsl)[l*2], g1 = ((const float4*)gsl)[l*2+1];
    float4 b0 = ((const float4*)bsl)[l*2], b1 = ((const float4*)bsl)[l*2+1];
    float gg[8] = {g0.x,g0.y,g0.z,g0.w,g1.x,g1.y,g1.z,g1.w};
    float bb[8] = {b0.x,b0.y,b0.z,b0.w,b1.x,b1.y,b1.z,b1.w};
    float4 m0a = ((const float4*)g_m0)[l*2], m0b = ((const float4*)g_m0)[l*2+1];
    float mm[8] = {m0a.x,m0a.y,m0a.z,m0a.w,m0b.x,m0b.y,m0b.z,m0b.w};
    float x[8];
    float p = 0.f;
#pragma unroll
    for (int i=0;i<8;i++){
        x[i] = (v[i]-m)*rstd*gg[i] + bb[i];
        p += x[i]*mm[i];
    }
#pragma unroll
    for (int o=16;o;o>>=1) p += __shfl_xor_sync(0xffffffffu, p, o);
    if (l==0) g_qk0[b*8+w] = p;
    __nv_bfloat162 h2[4];
#pragma unroll
    for (int i=0;i<4;i++)
        h2[i] = __halves2bfloat162(__float2bfloat16(x[2*i]), __float2bfloat16(x[2*i+1]));
    *(uint4*)(g_Xb + (size_t)(b*8+w)*256 + l*8) = *(uint4*)h2;
}

/* ------------- 4b. qk[512,256] = X @ M  (bf16 MMA GEMM) ----------------- */
#define LDSB 40
#define STG  20480
__global__ __launch_bounds__(256) void k_qk_mma(){
    extern __shared__ __align__(16) char smem_raw[];
    const unsigned sbase = smem_u32(smem_raw);
    const int tid  = threadIdx.x;
    const int warp = tid>>5, lane = tid&31;
    const int m0 = blockIdx.y*128;
    const int n0 = blockIdx.x*128;
    const int wm = (warp&3)*32;
    const int wn = (warp>>2)*64;

    float acc[2][8][4];
#pragma unroll
    for (int i=0;i<2;i++)
#pragma unroll
        for (int j=0;j<8;j++)
#pragma unroll
            for (int c=0;c<4;c++) acc[i][j][c]=0.f;

    auto load_stage = [&](int st, int k0){
        unsigned base = sbase + st*STG;
        int row = tid>>2, seg = tid&3;
#pragma unroll
        for (int p=0;p<2;p++){
            int r = row + p*64;
            size_t ga = ((size_t)(m0+r))*256 + k0 + seg*8;
            size_t gw = ((size_t)(n0+r))*256 + k0 + seg*8;
            unsigned dst = base + (unsigned)(r*80 + seg*16);
            cp16(dst,          g_Xb  + ga);
            cp16(dst + 10240,  g_MbT + gw);
        }
    };

#pragma unroll
    for (int s=0;s<3;s++){ load_stage(s, s*32); cp_commit(); }

#pragma unroll 1
    for (int kt=0; kt<8; kt++){
        if (kt < 6) cp_wait2();
        else if (kt == 6) cp_wait1();
        else cp_wait0();
        __syncthreads();
        if (kt < 5){ load_stage((kt+3)&3, (kt+3)*32); cp_commit(); }
        unsigned base = sbase + (kt&3)*STG;
#pragma unroll
        for (int ks=0; ks<32; ks+=16){
            unsigned ah[2][4];
#pragma unroll
            for (int mt=0;mt<2;mt++){
                unsigned addr = base + (unsigned)(((wm + mt*16 + (lane&15))*LDSB
                                         + ks + ((lane>>4)<<3))*2);
                ldm4(ah[mt][0],ah[mt][1],ah[mt][2],ah[mt][3], addr);
            }
            unsigned bh[4][4];
#pragma unroll
            for (int nt2=0;nt2<4;nt2++){
                unsigned addr = base + 10240u + (unsigned)(((wn + nt2*16 + (lane&15))*LDSB
                                         + ks + ((lane>>4)<<3))*2);
                ldm4(bh[nt2][0],bh[nt2][1],bh[nt2][2],bh[nt2][3], addr);
            }
#pragma unroll
            for (int mt=0;mt<2;mt++)
#pragma unroll
                for (int nt=0;nt<8;nt++){
                    int nt2 = nt>>1, pr = nt&1;
                    mma16816(acc[mt][nt], ah[mt], bh[nt2][pr], bh[nt2][pr+2]);
                }
        }
        __syncthreads();
    }
#pragma unroll
    for (int mt=0;mt<2;mt++){
        int r = m0 + wm + mt*16 + (lane>>2);
#pragma unroll
        for (int nt=0;nt<8;nt++){
            int nl = n0 + wn + nt*8 + (lane&3)*2;
            *(__nv_bfloat162*)(g_qkb + (size_t)r*256 + nl) = __halves2bfloat162(
                __float2bfloat16(acc[mt][nt][0]), __float2bfloat16(acc[mt][nt][1]));
            *(__nv_bfloat162*)(g_qkb + (size_t)(r+8)*256 + nl) = __halves2bfloat162(
                __float2bfloat16(acc[mt][nt][2]), __float2bfloat16(acc[mt][nt][3]));
        }
    }
}

/* ------------- 5. fused, warp-specialized, 64-token subtiles ------------ */
/* grid (8,64), 256 thr. warps 0-3: logits+softmax(st); warps 4-7: ux(st-1)*/
/* smem: 3 x-buffers (64x528B) + 2 attn buffers + csum + qk0 = ~104KB      */
#define TOKS2  64
#define LDSE   264                       /* bf16 elems per padded row */
#define XTB2   (TOKS2*LDSE*2)            /* 33792 B */
#define ATT2_OFF (3*XTB2)                /* 2 x [8][72] bf16 = 2x576 elems */
#define CS2_OFF  (ATT2_OFF + 2304)
#define QK02_OFF (CS2_OFF + 128)
#define SMEMB2   (QK02_OFF + 32)
__global__ __launch_bounds__(256) void k_fused(){
    extern __shared__ __align__(16) char sm[];
    __nv_bfloat16* attn_b = (__nv_bfloat16*)(sm + ATT2_OFF);
    float* csum_s = (float*)(sm + CS2_OFF);      /* [4 warps][8] */
    float* qk0s   = (float*)(sm + QK02_OFF);
    const unsigned sb = smem_u32(sm);
    const int b = blockIdx.y, chunk = blockIdx.x;
    const int t = threadIdx.x, w = t>>5, l = t&31;
    const int ww = w & 3;
    const bool p1 = (w < 4);
    const int col0 = (l&3)*2;

    unsigned bf[16][2];
    if (p1){
        const __nv_bfloat16* qkb = g_qkb + ((size_t)b*8 + (l>>2))*256 + col0;
#pragma unroll
        for (int s16=0;s16<16;s16++){
            bf[s16][0] = *(const unsigned*)(qkb + s16*16);
            bf[s16][1] = *(const unsigned*)(qkb + s16*16 + 8);
        }
    }
    if (t<8) qk0s[t] = g_qk0[b*8+t];

    float cs0=0.f, cs1=0.f;
    float ua[4][4];
#pragma unroll
    for (int i=0;i<4;i++)
#pragma unroll
        for (int j=0;j<4;j++) ua[i][j]=0.f;

    const size_t grow0 = (size_t)(b*NTOK + chunk*512);
    auto load_x = [&](int buf, int tok0){
        unsigned dstb = sb + (unsigned)(buf*XTB2);
        int rr = t>>2;
        int sg0 = (t&3)*8;
#pragma unroll
        for (int j=0;j<8;j++){
            int seg = sg0 + j;
            cp16(dstb + (unsigned)(rr*528 + seg*16),
                 g_Ah + (grow0 + tok0 + rr)*DIM + seg*8);
        }
    };
    load_x(0, 0); cp_commit();
    load_x(1, TOKS2); cp_commit();

#pragma unroll 1
    for (int st=0; st<9; st++){
        if (st<7) cp_wait1();
        else if (st==7) cp_wait0();
        __syncthreads();
        if (p1){
            if (st<8){
                unsigned xb = sb + (unsigned)((st%3)*XTB2);
                float cacc[4] = {0.f,0.f,0.f,0.f};
#pragma unroll
                for (int s16=0;s16<16;s16++){
                    unsigned a[4];
                    unsigned addr = xb + (unsigned)(((ww*16 + (l&15))*LDSE
                                       + s16*16 + ((l>>4)<<3))*2);
                    ldm4(a[0],a[1],a[2],a[3], addr);
                    mma16816(cacc, a, bf[s16][0], bf[s16][1]);
                }
                cacc[0] += qk0s[col0]; cacc[1] += qk0s[col0+1];
                cacc[2] += qk0s[col0]; cacc[3] += qk0s[col0+1];
                float m0 = fmaxf(cacc[0],cacc[1]), m1 = fmaxf(cacc[2],cacc[3]);
                m0 = fmaxf(m0, __shfl_xor_sync(0xffffffffu, m0, 1));
                m1 = fmaxf(m1, __shfl_xor_sync(0xffffffffu, m1, 1));
                m0 = fmaxf(m0, __shfl_xor_sync(0xffffffffu, m0, 2));
                m1 = fmaxf(m1, __shfl_xor_sync(0xffffffffu, m1, 2));
                float e0 = expf(cacc[0]-m0), e1 = expf(cacc[1]-m0);
                float e2 = expf(cacc[2]-m1), e3 = expf(cacc[3]-m1);
                float s0 = e0+e1, s1 = e2+e3;
                s0 += __shfl_xor_sync(0xffffffffu, s0, 1);
                s1 += __shfl_xor_sync(0xffffffffu, s1, 1);
                s0 += __shfl_xor_sync(0xffffffffu, s0, 2);
                s1 += __shfl_xor_sync(0xffffffffu, s1, 2);
                float i0 = 1.0f/s0, i1 = 1.0f/s1;
                float a0 = e0*i0+EPSA, a1 = e1*i0+EPSA;
                float a2 = e2*i1+EPSA, a3 = e3*i1+EPSA;
                cs0 += a0+a2; cs1 += a1+a3;
                __nv_bfloat16* atp = attn_b + (st&1)*576;
                int row = ww*16 + (l>>2);
                atp[col0*72 + row]         = __float2bfloat16(a0);
                atp[(col0+1)*72 + row]     = __float2bfloat16(a1);
                atp[col0*72 + row + 8]     = __float2bfloat16(a2);
                atp[(col0+1)*72 + row + 8] = __float2bfloat16(a3);
            }
        } else {
            if (st>=1){
                int sp = st-1;
                unsigned xb = sb + (unsigned)((sp%3)*XTB2);
                const __nv_bfloat16* atp = attn_b + (sp&1)*576;
#pragma unroll
                for (int kt=0; kt<4; kt++){
                    unsigned b0 = *(const unsigned*)&atp[(l>>2)*72 + kt*16 + (l&3)*2];
                    unsigned b1 = *(const unsigned*)&atp[(l>>2)*72 + kt*16 + 8 + (l&3)*2];
                    int tok = kt*16 + (l&7) + ((l>>4)<<3);
#pragma unroll
                    for (int mt=0; mt<4; mt++){
                        int dd = ww*64 + mt*16 + ((l>>3)&1)*8;
                        unsigned a[4];
                        ldm4t(a[0],a[1],a[2],a[3],
                              xb + (unsigned)((tok*LDSE + dd)*2));
                        mma16816(ua[mt], a, b0, b1);
                    }
                }
            }
        }
        __syncthreads();
        if (st<6){ load_x((st+2)%3, (st+2)*TOKS2); cp_commit(); }
    }
    /* colsum reduction from phase-1 warps */
    if (p1){
        cs0 += __shfl_xor_sync(0xffffffffu, cs0, 4);
        cs1 += __shfl_xor_sync(0xffffffffu, cs1, 4);
        cs0 += __shfl_xor_sync(0xffffffffu, cs0, 8);
        cs1 += __shfl_xor_sync(0xffffffffu, cs1, 8);
        cs0 += __shfl_xor_sync(0xffffffffu, cs0, 16);
        cs1 += __shfl_xor_sync(0xffffffffu, cs1, 16);
        if (l<4){ csum_s[ww*8 + col0] = cs0; csum_s[ww*8 + col0 + 1] = cs1; }
    }
    __syncthreads();
    if (t<8){
        float s=0.f;
#pragma unroll
        for (int i=0;i<4;i++) s += csum_s[i*8+t];
        g_cspart[(b*NCHUNK + chunk)*KSLOT + t] = s;
    }
    if (!p1){
        size_t base = ((size_t)chunk*BATCH*KSLOT) + b*8;
        int s0 = (l&3)*2;
#pragma unroll
        for (int mt=0;mt<4;mt++){
            int d0 = ww*64 + mt*16 + (l>>2);
            g_updpart[(base + s0  )*256 + d0]     = ua[mt][0];
            g_updpart[(base + s0+1)*256 + d0]     = ua[mt][1];
            g_updpart[(base + s0  )*256 + d0 + 8] = ua[mt][2];
            g_updpart[(base + s0+1)*256 + d0 + 8] = ua[mt][3];
        }
    }
}

/* ------------- 6. finalize updates + GRU + optional MLP (fp32) ---------- */
__global__ __launch_bounds__(256) void k_gru(
        const float* __restrict__ Wih, const float* __restrict__ Whh,
        const float* __restrict__ bih, const float* __restrict__ bhh,
        const float* __restrict__ W1,  const float* __restrict__ b1,
        const float* __restrict__ W2,  const float* __restrict__ b2,
        const float* __restrict__ gm,  const float* __restrict__ bm,
        int do_mlp, float* __restrict__ out){
    int t = threadIdx.x;
    int r0 = blockIdx.x * 4;
    __shared__ float Us[4][256];
    __shared__ float Xs[4][256];
    __shared__ float Hs[4][256];
    __shared__ float Hm[4][512];
    __shared__ float mred[4][2];
    __shared__ float csum[4];
#pragma unroll
    for (int r=0;r<4;r++){
        int gr = r0+r;
        float s=0.f;
#pragma unroll
        for (int cc=0;cc<NCHUNK;cc++)
            s += g_updpart[(((size_t)cc*BATCH*KSLOT) + gr)*256 + t];
        Us[r][t] = s;
        Hs[r][t] = g_slots[gr*256 + t];
    }
    if (t<4){
        int gr = r0+t, bb = gr>>3, kk = gr&7;
        float cs=0.f;
#pragma unroll
        for (int cc=0;cc<NCHUNK;cc++) cs += g_cspart[(bb*NCHUNK+cc)*KSLOT + kk];
        csum[t] = cs;
    }
    __syncthreads();
    {
        float acc[4] = {0,0,0,0};
        const uint4* wv = (const uint4*)(g_Wvf + (size_t)t*256);
#pragma unroll 4
        for (int s8=0;s8<32;s8++){
            uint4 raw = wv[s8];
            const __nv_bfloat162* p2 = (const __nv_bfloat162*)&raw;
#pragma unroll
            for (int j2=0;j2<4;j2++){
                float2 f = __bfloat1622float2(p2[j2]);
#pragma unroll
                for (int r=0;r<4;r++){
                    acc[r] += Us[r][s8*8+2*j2]  *f.x;
                    acc[r] += Us[r][s8*8+2*j2+1]*f.y;
                }
            }
        }
        float cbt = g_cbv[t];
#pragma unroll
        for (int r=0;r<4;r++) Xs[r][t] = acc[r]/csum[r] + cbt;
    }
    __syncthreads();

    float gi_[3][4], gh_[3][4];
#pragma unroll
    for (int g=0; g<3; g++){
        float ai[4]={0,0,0,0}, ah[4]={0,0,0,0};
        const float4* wi = (const float4*)(Wih + ((size_t)((g<<8)+t))*256);
        const float4* wh = (const float4*)(Whh + ((size_t)((g<<8)+t))*256);
#pragma unroll 4
        for (int d=0; d<64; d++){
            float4 a = wi[d], cc = wh[d];
#pragma unroll
            for (int r=0;r<4;r++){
                float4 xv = *(const float4*)&Xs[r][d<<2];
                float4 hv = *(const float4*)&Hs[r][d<<2];
                ai[r] += a.x*xv.x + a.y*xv.y + a.z*xv.z + a.w*xv.w;
                ah[r] += cc.x*hv.x + cc.y*hv.y + cc.z*hv.z + cc.w*hv.w;
            }
        }
        float bi = bih[(g<<8)+t], bh = bhh[(g<<8)+t];
#pragma unroll
        for (int r=0;r<4;r++){ gi_[g][r] = ai[r]+bi; gh_[g][r] = ah[r]+bh; }
    }
    __syncthreads();

    float newv[4];
#pragma unroll
    for (int r=0;r<4;r++){
        float hh = Hs[r][t];
        float rr = sigmoidf_(gi_[0][r] + gh_[0][r]);
        float zz = sigmoidf_(gi_[1][r] + gh_[1][r]);
        float nn = tanhf(gi_[2][r] + rr*gh_[2][r]);
        newv[r] = (1.0f - zz)*nn + zz*hh;
    }
#pragma unroll
    for (int r=0;r<4;r++) Xs[r][t] = newv[r];

    if (!do_mlp){
#pragma unroll
        for (int r=0;r<4;r++){
            g_slots[(r0+r)*256 + t] = newv[r];
            if (out) out[(r0+r)*256 + t] = newv[r];
        }
        return;
    }
    __syncthreads();
    int warp = t>>5, lane = t&31;
    if (warp < 4){
        float s=0.f, q=0.f;
#pragma unroll
        for (int j=0;j<8;j++){
            float xv = Xs[warp][lane + (j<<5)];
            s += xv; q += xv*xv;
        }
#pragma unroll
        for (int o=16;o;o>>=1){
            s += __shfl_xor_sync(0xffffffffu, s, o);
            q += __shfl_xor_sync(0xffffffffu, q, o);
        }
        if (lane==0){
            float m = s*(1.0f/256.f);
            mred[warp][0] = m;
            mred[warp][1] = rsqrtf(q*(1.0f/256.f) - m*m + LNEPS);
        }
    }
    __syncthreads();
    float gmt = gm[t], bmt = bm[t];
#pragma unroll
    for (int r=0;r<4;r++)
        Hs[r][t] = (Xs[r][t] - mred[r][0])*mred[r][1]*gmt + bmt;
    __syncthreads();
#pragma unroll
    for (int hblk=0; hblk<2; hblk++){
        int ho = t + (hblk<<8);
        float acc[4]={0,0,0,0};
        const float4* wp = (const float4*)(W1 + (size_t)ho*256);
#pragma unroll 4
        for (int d=0; d<64; d++){
            float4 a = wp[d];
#pragma unroll
            for (int r=0;r<4;r++)
                acc[r] += dot4_(a, *(const float4*)&Hs[r][d<<2]);
        }
        float bb = b1[ho];
#pragma unroll
        for (int r=0;r<4;r++) Hm[r][ho] = fmaxf(acc[r]+bb, 0.f);
    }
    __syncthreads();
    {
        float acc[4]={0,0,0,0};
        const float4* wp = (const float4*)(W2 + (size_t)t*512);
#pragma unroll 4
        for (int j=0; j<128; j++){
            float4 a = wp[j];
#pragma unroll
            for (int r=0;r<4;r++)
                acc[r] += dot4_(a, *(const float4*)&Hm[r][j<<2]);
        }
        float bb = b2[t];
#pragma unroll
        for (int r=0;r<4;r++)
            g_slots[(r0+r)*256 + t] = Xs[r][t] + acc[r] + bb;
    }
}

/* ----------------------------- launcher -------------------------------- */
extern "C" void kernel_launch(void* const* d_in, const int* in_sizes, int n_in,
                              void* d_out, int out_size){
    (void)in_sizes; (void)n_in; (void)out_size;
    const float* inputs = (const float*)d_in[0];
    const float* noise  = (const float*)d_in[1];
    const float* mu     = (const float*)d_in[2];
    const float* lsig   = (const float*)d_in[3];
    const float* gin    = (const float*)d_in[4];
    const float* bin    = (const float*)d_in[5];
    const float* gsl    = (const float*)d_in[6];
    const float* bsl    = (const float*)d_in[7];
    const float* gm     = (const float*)d_in[8];
    const float* bm     = (const float*)d_in[9];
    const float* Wq     = (const float*)d_in[10];
    const float* Wk     = (const float*)d_in[11];
    const float* Wv     = (const float*)d_in[12];
    const float* Wih    = (const float*)d_in[13];
    const float* Whh    = (const float*)d_in[14];
    const float* bih    = (const float*)d_in[15];
    const float* bhh    = (const float*)d_in[16];
    const float* W1     = (const float*)d_in[17];
    const float* b1     = (const float*)d_in[18];
    const float* W2     = (const float*)d_in[19];
    const float* b2     = (const float*)d_in[20];
    float* out = (float*)d_out;

    cudaFuncSetAttribute(k_fused,
                         cudaFuncAttributeMaxDynamicSharedMemorySize, SMEMB2);
    cudaFuncSetAttribute(k_qk_mma,
                         cudaFuncAttributeMaxDynamicSharedMemorySize, 4*STG);

    k_init_slots<<<512, 256>>>(noise, mu, lsig);
    k_prep_a<<<NROWS/8, 256>>>(inputs);
    k_prep_w<<<256, 256>>>(Wk, Wv, gin, bin);
    k_prep_m<<<dim3(4,4), 256>>>(Wq, Wk, gin);
    k_prep_m0<<<1, 256>>>(Wq);
    for (int it=0; it<3; it++){
        k_ln_slots<<<BATCH, 256>>>(gsl, bsl);
        k_qk_mma<<<dim3(2,4), 256, 4*STG>>>();
        k_fused<<<dim3(NCHUNK, BATCH), 256, SMEMB2>>>();
        k_gru<<<128, 256>>>(Wih, Whh, bih, bhh, W1, b1, W2, b2, gm, bm,
                            (it < 2) ? 1 : 0, (it == 2) ? out : nullptr);
    }
}

// round 17
// speedup vs baseline: 1.0910x; 1.0910x over previous
#include <cuda_runtime.h>
#include <cuda_bf16.h>
#include <math.h>
#include <stddef.h>

#define BATCH  64
#define NTOK   4096
#define DIM    256
#define SDIM   256
#define KSLOT  8
#define EPSA   1e-8f
#define LNEPS  1e-5f
#define NROWS  (BATCH*NTOK)       /* 262144 */
#define NCHUNK 8                  /* 512 tokens per chunk */

/* ------------- scratch (device globals; no allocation allowed) ---------- */
/* g_Ah layout: row-major [NROWS][256] bf16, but within each row the 16B    */
/* segment seg (0..31) is stored at position seg ^ (row & 7). Only writer   */
/* is k_prep_a; only reader is k_fused (both apply the same swizzle).       */
__device__ __align__(16) __nv_bfloat16 g_Ah[(size_t)NROWS*DIM];    /* 128 MB */
__device__ __align__(16) __nv_bfloat16 g_Wvf[256*256];
__device__ __align__(16) float g_cbk[256];
__device__ __align__(16) float g_cbv[256];
__device__ __align__(16) __nv_bfloat16 g_MbT[256*256];
__device__ __align__(16) float g_m0[256];
__device__ __align__(16) float g_slots[BATCH*KSLOT*SDIM];
__device__ __align__(16) __nv_bfloat16 g_Xb[512*256];
__device__ __align__(16) __nv_bfloat16 g_qkb[BATCH*KSLOT*DIM];
__device__ __align__(16) float g_qk0[BATCH*KSLOT];
__device__ __align__(16) float g_updpart[NCHUNK*BATCH*KSLOT*DIM];  /* 4 MB */
__device__ __align__(16) float g_cspart[BATCH*NCHUNK*KSLOT];

__device__ __forceinline__ float sigmoidf_(float x){ return 1.0f/(1.0f + expf(-x)); }
__device__ __forceinline__ float dot4_(float4 a, float4 b){
    return a.x*b.x + a.y*b.y + a.z*b.z + a.w*b.w;
}

/* ----------------------- PTX helpers ----------------------------------- */
__device__ __forceinline__ unsigned smem_u32(const void* p){
    return (unsigned)__cvta_generic_to_shared(p);
}
__device__ __forceinline__ void cp16(unsigned dst, const void* src){
    asm volatile("cp.async.cg.shared.global [%0],[%1],16;\n"::"r"(dst),"l"(src));
}
__device__ __forceinline__ void cp_commit(){ asm volatile("cp.async.commit_group;\n"::); }
__device__ __forceinline__ void cp_wait2(){ asm volatile("cp.async.wait_group 2;\n"::); }
__device__ __forceinline__ void cp_wait1(){ asm volatile("cp.async.wait_group 1;\n"::); }
__device__ __forceinline__ void cp_wait0(){ asm volatile("cp.async.wait_group 0;\n"::); }
__device__ __forceinline__ void ldm4(unsigned&r0,unsigned&r1,unsigned&r2,unsigned&r3,unsigned a){
    asm volatile("ldmatrix.sync.aligned.m8n8.x4.shared.b16 {%0,%1,%2,%3},[%4];\n"
        :"=r"(r0),"=r"(r1),"=r"(r2),"=r"(r3):"r"(a));
}
__device__ __forceinline__ void ldm4t(unsigned&r0,unsigned&r1,unsigned&r2,unsigned&r3,unsigned a){
    asm volatile("ldmatrix.sync.aligned.m8n8.x4.trans.shared.b16 {%0,%1,%2,%3},[%4];\n"
        :"=r"(r0),"=r"(r1),"=r"(r2),"=r"(r3):"r"(a));
}
__device__ __forceinline__ void mma16816(float* c, const unsigned* a, unsigned b0, unsigned b1){
    asm volatile("mma.sync.aligned.m16n8k16.row.col.f32.bf16.bf16.f32 "
        "{%0,%1,%2,%3},{%4,%5,%6,%7},{%8,%9},{%0,%1,%2,%3};\n"
        :"+f"(c[0]),"+f"(c[1]),"+f"(c[2]),"+f"(c[3])
        :"r"(a[0]),"r"(a[1]),"r"(a[2]),"r"(a[3]),"r"(b0),"r"(b1));
}
__device__ __forceinline__ void mbar_init(unsigned mbar, unsigned count){
    asm volatile("mbarrier.init.shared.b64 [%0], %1;" :: "r"(mbar), "r"(count) : "memory");
}
__device__ __forceinline__ void mbar_expect_tx(unsigned mbar, unsigned bytes){
    asm volatile("mbarrier.arrive.expect_tx.shared.b64 _, [%0], %1;"
        :: "r"(mbar), "r"(bytes) : "memory");
}
__device__ __forceinline__ void mbar_wait(unsigned mbar, unsigned parity){
    asm volatile(
        "{\n\t.reg .pred P;\n\t"
        "LW_%=:\n\t"
        "mbarrier.try_wait.parity.acquire.cta.shared::cta.b64 P, [%0], %1;\n\t"
        "@!P bra LW_%=;\n\t}"
        :: "r"(mbar), "r"(parity) : "memory");
}
__device__ __forceinline__ void bulk_ld(unsigned dst, const void* src,
                                        unsigned bytes, unsigned mbar){
    asm volatile(
        "cp.async.bulk.shared::cluster.global.mbarrier::complete_tx::bytes "
        "[%0], [%1], %2, [%3];"
        :: "r"(dst), "l"(src), "r"(bytes), "r"(mbar) : "memory");
}

/* ---------------------- 1. slots = mu + exp(ls)*noise ------------------- */
__global__ void k_init_slots(const float* __restrict__ noise,
                             const float* __restrict__ mu,
                             const float* __restrict__ lsig){
    int i = blockIdx.x*256 + threadIdx.x;
    int s = i & (SDIM-1);
    g_slots[i] = mu[s] + expf(lsig[s]) * noise[i];
}

/* ------------- 2. LN(inputs, no affine) -> bf16 (seg-swizzled) --------- */
__global__ __launch_bounds__(256) void k_prep_a(const float* __restrict__ inp){
    int row  = blockIdx.x*8 + (threadIdx.x >> 5);
    int lane = threadIdx.x & 31;
    const float4* p = (const float4*)(inp + (size_t)row*DIM);
    float4 a = p[lane*2], b = p[lane*2+1];
    float x[8] = {a.x,a.y,a.z,a.w,b.x,b.y,b.z,b.w};
    float s = 0.f, q = 0.f;
#pragma unroll
    for (int i=0;i<8;i++){ s += x[i]; q += x[i]*x[i]; }
#pragma unroll
    for (int o=16;o;o>>=1){
        s += __shfl_xor_sync(0xffffffffu, s, o);
        q += __shfl_xor_sync(0xffffffffu, q, o);
    }
    float m = s*(1.0f/DIM);
    float rstd = rsqrtf(q*(1.0f/DIM) - m*m + LNEPS);
    __nv_bfloat162 h2[4];
#pragma unroll
    for (int i=0;i<4;i++){
        h2[i] = __halves2bfloat162(__float2bfloat16((x[2*i]-m)*rstd),
                                   __float2bfloat16((x[2*i+1]-m)*rstd));
    }
    int segsw = lane ^ (row & 7);
    size_t off = (size_t)row*DIM + segsw*8;
    *(uint4*)(g_Ah + off) = *(uint4*)h2;
}

/* ------------- 3. weight prep: fold gamma/beta/scale -------------------- */
__global__ __launch_bounds__(256) void k_prep_w(const float* __restrict__ Wk,
        const float* __restrict__ Wv, const float* __restrict__ gin,
        const float* __restrict__ bin){
    __shared__ float rk[8], rv[8];
    int s = blockIdx.x, d = threadIdx.x;
    int w = d>>5, l = d&31;
    float gk = gin[d], bt = bin[d];
    float wk = Wk[s*256+d], wv = Wv[s*256+d];
    g_Wvf[s*256+d] = __float2bfloat16(wv*gk);
    float pk = wk*bt, pv = wv*bt;
#pragma unroll
    for (int o=16;o;o>>=1){
        pk += __shfl_xor_sync(0xffffffffu, pk, o);
        pv += __shfl_xor_sync(0xffffffffu, pv, o);
    }
    if (l==0){ rk[w]=pk; rv[w]=pv; }
    __syncthreads();
    if (d==0){
        float sk=0.f, sv=0.f;
#pragma unroll
        for (int i=0;i<8;i++){ sk+=rk[i]; sv+=rv[i]; }
        g_cbk[s] = sk*0.0625f;
        g_cbv[s] = sv;
    }
}

/* ------------- 3b. tiled GEMM: MbT[d][e] = Sum_s Wq[s,e]Wk[s,d]g[d]/16 -- */
__global__ __launch_bounds__(256) void k_prep_m(const float* __restrict__ Wq,
        const float* __restrict__ Wk, const float* __restrict__ gin){
    __shared__ float As[32][64];
    __shared__ float Bs[32][64];
    int e0 = blockIdx.x*64, d0 = blockIdx.y*64;
    int tid = threadIdx.x;
    int tx = tid&15, ty = tid>>4;
    int lr = tid>>3, lc = (tid&7)*8;
    float acc[4][4];
#pragma unroll
    for (int i=0;i<4;i++)
#pragma unroll
        for (int j=0;j<4;j++) acc[i][j]=0.f;
    for (int s0=0;s0<256;s0+=32){
        *(float4*)&As[lr][lc]   = *(const float4*)(Wq + (size_t)(s0+lr)*256 + e0 + lc);
        *(float4*)&As[lr][lc+4] = *(const float4*)(Wq + (size_t)(s0+lr)*256 + e0 + lc + 4);
        *(float4*)&Bs[lr][lc]   = *(const float4*)(Wk + (size_t)(s0+lr)*256 + d0 + lc);
        *(float4*)&Bs[lr][lc+4] = *(const float4*)(Wk + (size_t)(s0+lr)*256 + d0 + lc + 4);
        __syncthreads();
#pragma unroll
        for (int s=0;s<32;s++){
            float4 av = *(const float4*)&As[s][ty*4];
            float4 bv = *(const float4*)&Bs[s][tx*4];
            float a[4] = {av.x,av.y,av.z,av.w};
            float b[4] = {bv.x,bv.y,bv.z,bv.w};
#pragma unroll
            for (int i=0;i<4;i++)
#pragma unroll
                for (int j=0;j<4;j++) acc[i][j] += a[i]*b[j];
        }
        __syncthreads();
    }
#pragma unroll
    for (int j=0;j<4;j++){
        int d = d0 + tx*4 + j;
        float gd = gin[d]*0.0625f;
        __nv_bfloat162 p0 = __halves2bfloat162(
            __float2bfloat16(acc[0][j]*gd), __float2bfloat16(acc[1][j]*gd));
        __nv_bfloat162 p1 = __halves2bfloat162(
            __float2bfloat16(acc[2][j]*gd), __float2bfloat16(acc[3][j]*gd));
        *(__nv_bfloat162*)(g_MbT + (size_t)d*256 + e0 + ty*4)     = p0;
        *(__nv_bfloat162*)(g_MbT + (size_t)d*256 + e0 + ty*4 + 2) = p1;
    }
}

/* ------------- 3c. m0[e] = Sum_s Wq[s,e]*cbk[s]  (1 block) -------------- */
__global__ __launch_bounds__(256) void k_prep_m0(const float* __restrict__ Wq){
    __shared__ float cb[256];
    int e = threadIdx.x;
    cb[e] = g_cbk[e];
    __syncthreads();
    float p=0.f;
#pragma unroll 4
    for (int s=0;s<256;s++) p += Wq[(size_t)s*256+e]*cb[s];
    g_m0[e] = p;
}

/* ------------- 4a. X = LN(slots)*gsl+bsl -> bf16 ; qk0 = X·m0 ----------- */
__global__ __launch_bounds__(256) void k_ln_slots(const float* __restrict__ gsl,
                                                  const float* __restrict__ bsl){
    int b = blockIdx.x, t = threadIdx.x, w = t>>5, l = t&31;
    const float4* sr = (const float4*)(g_slots + (b*8+w)*256);
    float4 a = sr[l*2], c = sr[l*2+1];
    float v[8] = {a.x,a.y,a.z,a.w,c.x,c.y,c.z,c.w};
    float s=0.f, q=0.f;
#pragma unroll
    for (int i=0;i<8;i++){ s+=v[i]; q+=v[i]*v[i]; }
#pragma unroll
    for (int o=16;o;o>>=1){
        s += __shfl_xor_sync(0xffffffffu, s, o);
        q += __shfl_xor_sync(0xffffffffu, q, o);
    }
    float m = s*(1.0f/256.f);
    float rstd = rsqrtf(q*(1.0f/256.f)-m*m+LNEPS);
    float4 g0 = ((const float4*)gsl)[l*2], g1 = ((const float4*)gsl)[l*2+1];
    float4 b0 = ((const float4*)bsl)[l*2], b1 = ((const float4*)bsl)[l*2+1];
    float gg[8] = {g0.x,g0.y,g0.z,g0.w,g1.x,g1.y,g1.z,g1.w};
    float bb[8] = {b0.x,b0.y,b0.z,b0.w,b1.x,b1.y,b1.z,b1.w};
    float4 m0a = ((const float4*)g_m0)[l*2], m0b = ((const float4*)g_m0)[l*2+1];
    float mm[8] = {m0a.x,m0a.y,m0a.z,m0a.w,m0b.x,m0b.y,m0b.z,m0b.w};
    float x[8];
    float p = 0.f;
#pragma unroll
    for (int i=0;i<8;i++){
        x[i] = (v[i]-m)*rstd*gg[i] + bb[i];
        p += x[i]*mm[i];
    }
#pragma unroll
    for (int o=16;o;o>>=1) p += __shfl_xor_sync(0xffffffffu, p, o);
    if (l==0) g_qk0[b*8+w] = p;
    __nv_bfloat162 h2[4];
#pragma unroll
    for (int i=0;i<4;i++)
        h2[i] = __halves2bfloat162(__float2bfloat16(x[2*i]), __float2bfloat16(x[2*i+1]));
    *(uint4*)(g_Xb + (size_t)(b*8+w)*256 + l*8) = *(uint4*)h2;
}

/* ------------- 4b. qk[512,256] = X @ M  (bf16 MMA GEMM) ----------------- */
#define LDSB 40
#define STG  20480
__global__ __launch_bounds__(256) void k_qk_mma(){
    extern __shared__ __align__(16) char smem_raw[];
    const unsigned sbase = smem_u32(smem_raw);
    const int tid  = threadIdx.x;
    const int warp = tid>>5, lane = tid&31;
    const int m0 = blockIdx.y*128;
    const int n0 = blockIdx.x*128;
    const int wm = (warp&3)*32;
    const int wn = (warp>>2)*64;

    float acc[2][8][4];
#pragma unroll
    for (int i=0;i<2;i++)
#pragma unroll
        for (int j=0;j<8;j++)
#pragma unroll
            for (int c=0;c<4;c++) acc[i][j][c]=0.f;

    auto load_stage = [&](int st, int k0){
        unsigned base = sbase + st*STG;
        int row = tid>>2, seg = tid&3;
#pragma unroll
        for (int p=0;p<2;p++){
            int r = row + p*64;
            size_t ga = ((size_t)(m0+r))*256 + k0 + seg*8;
            size_t gw = ((size_t)(n0+r))*256 + k0 + seg*8;
            unsigned dst = base + (unsigned)(r*80 + seg*16);
            cp16(dst,          g_Xb  + ga);
            cp16(dst + 10240,  g_MbT + gw);
        }
    };

#pragma unroll
    for (int s=0;s<3;s++){ load_stage(s, s*32); cp_commit(); }

#pragma unroll 1
    for (int kt=0; kt<8; kt++){
        if (kt < 6) cp_wait2();
        else if (kt == 6) cp_wait1();
        else cp_wait0();
        __syncthreads();
        if (kt < 5){ load_stage((kt+3)&3, (kt+3)*32); cp_commit(); }
        unsigned base = sbase + (kt&3)*STG;
#pragma unroll
        for (int ks=0; ks<32; ks+=16){
            unsigned ah[2][4];
#pragma unroll
            for (int mt=0;mt<2;mt++){
                unsigned addr = base + (unsigned)(((wm + mt*16 + (lane&15))*LDSB
                                         + ks + ((lane>>4)<<3))*2);
                ldm4(ah[mt][0],ah[mt][1],ah[mt][2],ah[mt][3], addr);
            }
            unsigned bh[4][4];
#pragma unroll
            for (int nt2=0;nt2<4;nt2++){
                unsigned addr = base + 10240u + (unsigned)(((wn + nt2*16 + (lane&15))*LDSB
                                         + ks + ((lane>>4)<<3))*2);
                ldm4(bh[nt2][0],bh[nt2][1],bh[nt2][2],bh[nt2][3], addr);
            }
#pragma unroll
            for (int mt=0;mt<2;mt++)
#pragma unroll
                for (int nt=0;nt<8;nt++){
                    int nt2 = nt>>1, pr = nt&1;
                    mma16816(acc[mt][nt], ah[mt], bh[nt2][pr], bh[nt2][pr+2]);
                }
        }
        __syncthreads();
    }
#pragma unroll
    for (int mt=0;mt<2;mt++){
        int r = m0 + wm + mt*16 + (lane>>2);
#pragma unroll
        for (int nt=0;nt<8;nt++){
            int nl = n0 + wn + nt*8 + (lane&3)*2;
            *(__nv_bfloat162*)(g_qkb + (size_t)r*256 + nl) = __halves2bfloat162(
                __float2bfloat16(acc[mt][nt][0]), __float2bfloat16(acc[mt][nt][1]));
            *(__nv_bfloat162*)(g_qkb + (size_t)(r+8)*256 + nl) = __halves2bfloat162(
                __float2bfloat16(acc[mt][nt][2]), __float2bfloat16(acc[mt][nt][3]));
        }
    }
}

/* ------------- 5. fused, warp-specialized, bulk-copy loads -------------- */
/* grid (8,64), 256 thr. warps 0-3: logits+softmax(st); warps 4-7: ux(st-1)*/
/* x buffers: 3 x 32KB unpadded (seg-swizzle handles banks); ~100.8KB smem */
#define TOKS2  64
#define XBUF   32768                     /* 64 tokens x 512 B */
#define ATT2_OFF (3*XBUF)                /* 2 x [8][72] bf16 = 2x576 elems */
#define CS2_OFF  (ATT2_OFF + 2304)
#define QK02_OFF (CS2_OFF + 128)
#define MBAR_OFF (QK02_OFF + 32)
#define SMEMB2   (MBAR_OFF + 32)
__global__ __launch_bounds__(256) void k_fused(){
    extern __shared__ __align__(16) char sm[];
    __nv_bfloat16* attn_b = (__nv_bfloat16*)(sm + ATT2_OFF);
    float* csum_s = (float*)(sm + CS2_OFF);      /* [4 warps][8] */
    float* qk0s   = (float*)(sm + QK02_OFF);
    const unsigned sb = smem_u32(sm);
    const unsigned mb = sb + MBAR_OFF;
    const int b = blockIdx.y, chunk = blockIdx.x;
    const int t = threadIdx.x, w = t>>5, l = t&31;
    const int ww = w & 3;
    const bool p1 = (w < 4);
    const int col0 = (l&3)*2;

    unsigned bf[16][2];
    if (p1){
        const __nv_bfloat16* qkb = g_qkb + ((size_t)b*8 + (l>>2))*256 + col0;
#pragma unroll
        for (int s16=0;s16<16;s16++){
            bf[s16][0] = *(const unsigned*)(qkb + s16*16);
            bf[s16][1] = *(const unsigned*)(qkb + s16*16 + 8);
        }
    }
    if (t<8) qk0s[t] = g_qk0[b*8+t];

    float cs0=0.f, cs1=0.f;
    float ua[4][4];
#pragma unroll
    for (int i=0;i<4;i++)
#pragma unroll
        for (int j=0;j<4;j++) ua[i][j]=0.f;

    const size_t grow0 = (size_t)(b*NTOK + chunk*512);
    if (t==0){
        mbar_init(mb+0, 1);
        mbar_init(mb+8, 1);
        mbar_init(mb+16, 1);
    }
    __syncthreads();
    if (t==0){
        mbar_expect_tx(mb+0, XBUF);
        bulk_ld(sb+0,    g_Ah + grow0*DIM,              XBUF, mb+0);
        mbar_expect_tx(mb+8, XBUF);
        bulk_ld(sb+XBUF, g_Ah + (grow0+TOKS2)*DIM,      XBUF, mb+8);
    }

#pragma unroll 1
    for (int st=0; st<9; st++){
        if (st<8) mbar_wait(mb + (unsigned)((st%3)*8), (unsigned)((st/3)&1));
        __syncthreads();
        if (p1){
            if (st<8){
                unsigned xb = sb + (unsigned)((st%3)*XBUF);
                float cacc[4] = {0.f,0.f,0.f,0.f};
#pragma unroll
                for (int s16=0;s16<16;s16++){
                    int tokL = ww*16 + (l&15);
                    int seg  = s16*2 + (l>>4);
                    int segw = seg ^ (tokL & 7);
                    unsigned a[4];
                    ldm4(a[0],a[1],a[2],a[3],
                         xb + (unsigned)(tokL*512 + segw*16));
                    mma16816(cacc, a, bf[s16][0], bf[s16][1]);
                }
                cacc[0] += qk0s[col0]; cacc[1] += qk0s[col0+1];
                cacc[2] += qk0s[col0]; cacc[3] += qk0s[col0+1];
                float m0 = fmaxf(cacc[0],cacc[1]), m1 = fmaxf(cacc[2],cacc[3]);
                m0 = fmaxf(m0, __shfl_xor_sync(0xffffffffu, m0, 1));
                m1 = fmaxf(m1, __shfl_xor_sync(0xffffffffu, m1, 1));
                m0 = fmaxf(m0, __shfl_xor_sync(0xffffffffu, m0, 2));
                m1 = fmaxf(m1, __shfl_xor_sync(0xffffffffu, m1, 2));
                float e0 = expf(cacc[0]-m0), e1 = expf(cacc[1]-m0);
                float e2 = expf(cacc[2]-m1), e3 = expf(cacc[3]-m1);
                float s0 = e0+e1, s1 = e2+e3;
                s0 += __shfl_xor_sync(0xffffffffu, s0, 1);
                s1 += __shfl_xor_sync(0xffffffffu, s1, 1);
                s0 += __shfl_xor_sync(0xffffffffu, s0, 2);
                s1 += __shfl_xor_sync(0xffffffffu, s1, 2);
                float i0 = 1.0f/s0, i1 = 1.0f/s1;
                float a0 = e0*i0+EPSA, a1 = e1*i0+EPSA;
                float a2 = e2*i1+EPSA, a3 = e3*i1+EPSA;
                cs0 += a0+a2; cs1 += a1+a3;
                __nv_bfloat16* atp = attn_b + (st&1)*576;
                int row = ww*16 + (l>>2);
                atp[col0*72 + row]         = __float2bfloat16(a0);
                atp[(col0+1)*72 + row]     = __float2bfloat16(a1);
                atp[col0*72 + row + 8]     = __float2bfloat16(a2);
                atp[(col0+1)*72 + row + 8] = __float2bfloat16(a3);
            }
        } else {
            if (st>=1){
                int sp = st-1;
                unsigned xb = sb + (unsigned)((sp%3)*XBUF);
                const __nv_bfloat16* atp = attn_b + (sp&1)*576;
#pragma unroll
                for (int kt=0; kt<4; kt++){
                    unsigned b0 = *(const unsigned*)&atp[(l>>2)*72 + kt*16 + (l&3)*2];
                    unsigned b1 = *(const unsigned*)&atp[(l>>2)*72 + kt*16 + 8 + (l&3)*2];
                    int tok = kt*16 + (l&7) + ((l>>4)<<3);
#pragma unroll
                    for (int mt=0; mt<4; mt++){
                        int dd = ww*64 + mt*16 + ((l>>3)&1)*8;
                        int segw = (dd>>3) ^ (tok & 7);
                        unsigned a[4];
                        ldm4t(a[0],a[1],a[2],a[3],
                              xb + (unsigned)(tok*512 + segw*16));
                        mma16816(ua[mt], a, b0, b1);
                    }
                }
            }
        }
        __syncthreads();
        if (t==0 && st<6){
            unsigned mbx = mb + (unsigned)(((st+2)%3)*8);
            mbar_expect_tx(mbx, XBUF);
            bulk_ld(sb + (unsigned)(((st+2)%3)*XBUF),
                    g_Ah + (grow0 + (size_t)(st+2)*TOKS2)*DIM, XBUF, mbx);
        }
    }
    /* colsum reduction from phase-1 warps */
    if (p1){
        cs0 += __shfl_xor_sync(0xffffffffu, cs0, 4);
        cs1 += __shfl_xor_sync(0xffffffffu, cs1, 4);
        cs0 += __shfl_xor_sync(0xffffffffu, cs0, 8);
        cs1 += __shfl_xor_sync(0xffffffffu, cs1, 8);
        cs0 += __shfl_xor_sync(0xffffffffu, cs0, 16);
        cs1 += __shfl_xor_sync(0xffffffffu, cs1, 16);
        if (l<4){ csum_s[ww*8 + col0] = cs0; csum_s[ww*8 + col0 + 1] = cs1; }
    }
    __syncthreads();
    if (t<8){
        float s=0.f;
#pragma unroll
        for (int i=0;i<4;i++) s += csum_s[i*8+t];
        g_cspart[(b*NCHUNK + chunk)*KSLOT + t] = s;
    }
    if (!p1){
        size_t base = ((size_t)chunk*BATCH*KSLOT) + b*8;
        int s0 = (l&3)*2;
#pragma unroll
        for (int mt=0;mt<4;mt++){
            int d0 = ww*64 + mt*16 + (l>>2);
            g_updpart[(base + s0  )*256 + d0]     = ua[mt][0];
            g_updpart[(base + s0+1)*256 + d0]     = ua[mt][1];
            g_updpart[(base + s0  )*256 + d0 + 8] = ua[mt][2];
            g_updpart[(base + s0+1)*256 + d0 + 8] = ua[mt][3];
        }
    }
}

/* ------------- 6. finalize updates + GRU + optional MLP (fp32) ---------- */
__global__ __launch_bounds__(256) void k_gru(
        const float* __restrict__ Wih, const float* __restrict__ Whh,
        const float* __restrict__ bih, const float* __restrict__ bhh,
        const float* __restrict__ W1,  const float* __restrict__ b1,
        const float* __restrict__ W2,  const float* __restrict__ b2,
        const float* __restrict__ gm,  const float* __restrict__ bm,
        int do_mlp, float* __restrict__ out){
    int t = threadIdx.x;
    int r0 = blockIdx.x * 4;
    __shared__ float Us[4][256];
    __shared__ float Xs[4][256];
    __shared__ float Hs[4][256];
    __shared__ float Hm[4][512];
    __shared__ float mred[4][2];
    __shared__ float csum[4];
#pragma unroll
    for (int r=0;r<4;r++){
        int gr = r0+r;
        float s=0.f;
#pragma unroll
        for (int cc=0;cc<NCHUNK;cc++)
            s += g_updpart[(((size_t)cc*BATCH*KSLOT) + gr)*256 + t];
        Us[r][t] = s;
        Hs[r][t] = g_slots[gr*256 + t];
    }
    if (t<4){
        int gr = r0+t, bb = gr>>3, kk = gr&7;
        float cs=0.f;
#pragma unroll
        for (int cc=0;cc<NCHUNK;cc++) cs += g_cspart[(bb*NCHUNK+cc)*KSLOT + kk];
        csum[t] = cs;
    }
    __syncthreads();
    {
        float acc[4] = {0,0,0,0};
        const uint4* wv = (const uint4*)(g_Wvf + (size_t)t*256);
#pragma unroll 4
        for (int s8=0;s8<32;s8++){
            uint4 raw = wv[s8];
            const __nv_bfloat162* p2 = (const __nv_bfloat162*)&raw;
#pragma unroll
            for (int j2=0;j2<4;j2++){
                float2 f = __bfloat1622float2(p2[j2]);
#pragma unroll
                for (int r=0;r<4;r++){
                    acc[r] += Us[r][s8*8+2*j2]  *f.x;
                    acc[r] += Us[r][s8*8+2*j2+1]*f.y;
                }
            }
        }
        float cbt = g_cbv[t];
#pragma unroll
        for (int r=0;r<4;r++) Xs[r][t] = acc[r]/csum[r] + cbt;
    }
    __syncthreads();

    float gi_[3][4], gh_[3][4];
#pragma unroll
    for (int g=0; g<3; g++){
        float ai[4]={0,0,0,0}, ah[4]={0,0,0,0};
        const float4* wi = (const float4*)(Wih + ((size_t)((g<<8)+t))*256);
        const float4* wh = (const float4*)(Whh + ((size_t)((g<<8)+t))*256);
#pragma unroll 4
        for (int d=0; d<64; d++){
            float4 a = wi[d], cc = wh[d];
#pragma unroll
            for (int r=0;r<4;r++){
                float4 xv = *(const float4*)&Xs[r][d<<2];
                float4 hv = *(const float4*)&Hs[r][d<<2];
                ai[r] += a.x*xv.x + a.y*xv.y + a.z*xv.z + a.w*xv.w;
                ah[r] += cc.x*hv.x + cc.y*hv.y + cc.z*hv.z + cc.w*hv.w;
            }
        }
        float bi = bih[(g<<8)+t], bh = bhh[(g<<8)+t];
#pragma unroll
        for (int r=0;r<4;r++){ gi_[g][r] = ai[r]+bi; gh_[g][r] = ah[r]+bh; }
    }
    __syncthreads();

    float newv[4];
#pragma unroll
    for (int r=0;r<4;r++){
        float hh = Hs[r][t];
        float rr = sigmoidf_(gi_[0][r] + gh_[0][r]);
        float zz = sigmoidf_(gi_[1][r] + gh_[1][r]);
        float nn = tanhf(gi_[2][r] + rr*gh_[2][r]);
        newv[r] = (1.0f - zz)*nn + zz*hh;
    }
#pragma unroll
    for (int r=0;r<4;r++) Xs[r][t] = newv[r];

    if (!do_mlp){
#pragma unroll
        for (int r=0;r<4;r++){
            g_slots[(r0+r)*256 + t] = newv[r];
            if (out) out[(r0+r)*256 + t] = newv[r];
        }
        return;
    }
    __syncthreads();
    int warp = t>>5, lane = t&31;
    if (warp < 4){
        float s=0.f, q=0.f;
#pragma unroll
        for (int j=0;j<8;j++){
            float xv = Xs[warp][lane + (j<<5)];
            s += xv; q += xv*xv;
        }
#pragma unroll
        for (int o=16;o;o>>=1){
            s += __shfl_xor_sync(0xffffffffu, s, o);
            q += __shfl_xor_sync(0xffffffffu, q, o);
        }
        if (lane==0){
            float m = s*(1.0f/256.f);
            mred[warp][0] = m;
            mred[warp][1] = rsqrtf(q*(1.0f/256.f) - m*m + LNEPS);
        }
    }
    __syncthreads();
    float gmt = gm[t], bmt = bm[t];
#pragma unroll
    for (int r=0;r<4;r++)
        Hs[r][t] = (Xs[r][t] - mred[r][0])*mred[r][1]*gmt + bmt;
    __syncthreads();
#pragma unroll
    for (int hblk=0; hblk<2; hblk++){
        int ho = t + (hblk<<8);
        float acc[4]={0,0,0,0};
        const float4* wp = (const float4*)(W1 + (size_t)ho*256);
#pragma unroll 4
        for (int d=0; d<64; d++){
            float4 a = wp[d];
#pragma unroll
            for (int r=0;r<4;r++)
                acc[r] += dot4_(a, *(const float4*)&Hs[r][d<<2]);
        }
        float bb = b1[ho];
#pragma unroll
        for (int r=0;r<4;r++) Hm[r][ho] = fmaxf(acc[r]+bb, 0.f);
    }
    __syncthreads();
    {
        float acc[4]={0,0,0,0};
        const float4* wp = (const float4*)(W2 + (size_t)t*512);
#pragma unroll 4
        for (int j=0; j<128; j++){
            float4 a = wp[j];
#pragma unroll
            for (int r=0;r<4;r++)
                acc[r] += dot4_(a, *(const float4*)&Hm[r][j<<2]);
        }
        float bb = b2[t];
#pragma unroll
        for (int r=0;r<4;r++)
            g_slots[(r0+r)*256 + t] = Xs[r][t] + acc[r] + bb;
    }
}

/* ----------------------------- launcher -------------------------------- */
extern "C" void kernel_launch(void* const* d_in, const int* in_sizes, int n_in,
                              void* d_out, int out_size){
    (void)in_sizes; (void)n_in; (void)out_size;
    const float* inputs = (const float*)d_in[0];
    const float* noise  = (const float*)d_in[1];
    const float* mu     = (const float*)d_in[2];
    const float* lsig   = (const float*)d_in[3];
    const float* gin    = (const float*)d_in[4];
    const float* bin    = (const float*)d_in[5];
    const float* gsl    = (const float*)d_in[6];
    const float* bsl    = (const float*)d_in[7];
    const float* gm     = (const float*)d_in[8];
    const float* bm     = (const float*)d_in[9];
    const float* Wq     = (const float*)d_in[10];
    const float* Wk     = (const float*)d_in[11];
    const float* Wv     = (const float*)d_in[12];
    const float* Wih    = (const float*)d_in[13];
    const float* Whh    = (const float*)d_in[14];
    const float* bih    = (const float*)d_in[15];
    const float* bhh    = (const float*)d_in[16];
    const float* W1     = (const float*)d_in[17];
    const float* b1     = (const float*)d_in[18];
    const float* W2     = (const float*)d_in[19];
    const float* b2     = (const float*)d_in[20];
    float* out = (float*)d_out;

    cudaFuncSetAttribute(k_fused,
                         cudaFuncAttributeMaxDynamicSharedMemorySize, SMEMB2);
    cudaFuncSetAttribute(k_qk_mma,
                         cudaFuncAttributeMaxDynamicSharedMemorySize, 4*STG);

    k_init_slots<<<512, 256>>>(noise, mu, lsig);
    k_prep_a<<<NROWS/8, 256>>>(inputs);
    k_prep_w<<<256, 256>>>(Wk, Wv, gin, bin);
    k_prep_m<<<dim3(4,4), 256>>>(Wq, Wk, gin);
    k_prep_m0<<<1, 256>>>(Wq);
    for (int it=0; it<3; it++){
        k_ln_slots<<<BATCH, 256>>>(gsl, bsl);
        k_qk_mma<<<dim3(2,4), 256, 4*STG>>>();
        k_fused<<<dim3(NCHUNK, BATCH), 256, SMEMB2>>>();
        k_gru<<<128, 256>>>(Wih, Whh, bih, bhh, W1, b1, W2, b2, gm, bm,
                            (it < 2) ? 1 : 0, (it == 2) ? out : nullptr);
    }
}